// round 12
// baseline (speedup 1.0000x reference)
#include <cuda_runtime.h>
#include <cuda_bf16.h>
#include <math.h>
#include <cstdint>

#define NN   50000
#define EE   600000
#define HIDN 128
#define HH   4
#define DDIM 32
#define RR   4
#define LLAY 2
#define MMOUT 10000
#define NSEG (NN * RR)
#define SCAN_CHUNK 4096
#define SCAN_B ((NSEG + SCAN_CHUNK - 1) / SCAN_CHUNK)   // 49
#define EA_BLOCKS 592
#define EA_WARPS (EA_BLOCKS * 8)

typedef unsigned long long u64;

// ---------------- scratch ----------------
__device__ float g_h[NN * HIDN];
__device__ float g_q[NN * HIDN];
__device__ float g_k[NN * HIDN];
__device__ float g_v[NN * HIDN];
__device__ float g_qr[NN * RR * HIDN];   // A_r^T q : [n][r][h][d]
__device__ float g_attn[NN * HIDN];
__device__ float g_stats[2 * HIDN];
__device__ int   g_counts[NSEG];
__device__ int   g_offs[NSEG + 1];
__device__ int   g_cursor[NSEG];
__device__ int   g_bsum[SCAN_B];
__device__ int   g_boff[SCAN_B];
__device__ int   g_ssrc[EE];
// transposed bf16 hi/lo weight images: 9 matrices x (hi[n][k] 16384 + lo[n][k] 16384)
__device__ __nv_bfloat16 g_wimg[9 * 32768];

// ---------------- f32x2 helpers ----------------
__device__ __forceinline__ void fma2(u64& d, u64 a, u64 b) {
    asm("fma.rn.f32x2 %0, %1, %2, %0;" : "+l"(d) : "l"(a), "l"(b));
}
__device__ __forceinline__ u64 packdup(float s) {
    u64 r; asm("mov.b64 %0, {%1, %1};" : "=l"(r) : "f"(s)); return r;
}
__device__ __forceinline__ void unpack2(u64 v, float& lo, float& hi) {
    asm("mov.b64 {%0, %1}, %2;" : "=f"(lo), "=f"(hi) : "l"(v));
}
__device__ __forceinline__ float gelu_f(float x) {
    return 0.5f * x * (1.0f + erff(x * 0.7071067811865475f));
}

// ---------------- mma / ldmatrix / cp.async helpers ----------------
__device__ __forceinline__ void mma16816(float* c, const uint32_t* a, uint32_t b0, uint32_t b1) {
    asm volatile(
        "mma.sync.aligned.m16n8k16.row.col.f32.bf16.bf16.f32 "
        "{%0,%1,%2,%3}, {%4,%5,%6,%7}, {%8,%9}, {%0,%1,%2,%3};"
        : "+f"(c[0]), "+f"(c[1]), "+f"(c[2]), "+f"(c[3])
        : "r"(a[0]), "r"(a[1]), "r"(a[2]), "r"(a[3]), "r"(b0), "r"(b1));
}
__device__ __forceinline__ void ldsm_x4(uint32_t* r, uint32_t addr) {
    asm volatile("ldmatrix.sync.aligned.m8n8.x4.shared.b16 {%0,%1,%2,%3}, [%4];"
                 : "=r"(r[0]), "=r"(r[1]), "=r"(r[2]), "=r"(r[3]) : "r"(addr));
}
__device__ __forceinline__ uint32_t smem_to_u32(const void* p) {
    uint32_t a;
    asm("{ .reg .u64 t; cvta.to.shared.u64 t, %1; cvt.u32.u64 %0, t; }" : "=r"(a) : "l"(p));
    return a;
}
__device__ __forceinline__ void cp_async16(uint32_t dst, const void* src) {
    asm volatile("cp.async.cg.shared.global [%0], [%1], 16;" :: "r"(dst), "l"(src));
}
__device__ __forceinline__ void cp_async_commit() {
    asm volatile("cp.async.commit_group;" ::: "memory");
}
__device__ __forceinline__ void cp_async_wait0() {
    asm volatile("cp.async.wait_group 0;" ::: "memory");
}

// K-chunked GEMM smem layout
#define AST2 144
#define GS_AHI 0
#define GS_ALO (128 * AST2)
#define GS_BHI (2 * 128 * AST2)
#define GS_BLO (3 * 128 * AST2)
#define GS_TOTAL (4 * 128 * AST2)    // 73728

// ---------------- fill ----------------
__global__ void fill_zero_kernel(unsigned* __restrict__ p, int n) {
    int i = blockIdx.x * blockDim.x + threadIdx.x;
    if (i < n) p[i] = 0u;
}

// ================= weight prep =================
__global__ __launch_bounds__(128)
void wprep_kernel(const float* __restrict__ proj_w, const float* __restrict__ q_w,
                  const float* __restrict__ k_w, const float* __restrict__ v_w,
                  const float* __restrict__ a_w) {
    __shared__ float ws[64 * 128];
    int b = blockIdx.x, tid = threadIdx.x;
    const float* W;
    if (b == 0)      W = proj_w;
    else if (b <= 2) W = q_w + (size_t)(b - 1) * 16384;
    else if (b <= 4) W = k_w + (size_t)(b - 3) * 16384;
    else if (b <= 6) W = v_w + (size_t)(b - 5) * 16384;
    else             W = a_w + (size_t)(b - 7) * 16384;
    __nv_bfloat16* imgh = g_wimg + (size_t)b * 32768;
    __nv_bfloat16* imgl = imgh + 16384;

    for (int chunk = 0; chunk < 2; chunk++) {
        __syncthreads();
        for (int i = tid; i < 64 * 32; i += 128)
            ((float4*)ws)[i] = ((const float4*)(W + chunk * 64 * 128))[i];
        __syncthreads();
        int n = tid;
#pragma unroll
        for (int kk = 0; kk < 64; kk += 4) {
            __nv_bfloat16 h4[4], l4[4];
#pragma unroll
            for (int t = 0; t < 4; t++) {
                float v = ws[(kk + t) * 128 + n];
                __nv_bfloat16 hh = __float2bfloat16(v);
                h4[t] = hh;
                l4[t] = __float2bfloat16(v - __bfloat162float(hh));
            }
            *(uint2*)(imgh + n * 128 + chunk * 64 + kk) = *(uint2*)h4;
            *(uint2*)(imgl + n * 128 + chunk * 64 + kk) = *(uint2*)l4;
        }
    }
}

// ================= tensor-core GEMM (K-chunked, cp.async B staging) =================
template <int MODE>
__global__ __launch_bounds__(256, 2)
void gemm_tc(const float* __restrict__ A,
             const __nv_bfloat16* __restrict__ I0, const __nv_bfloat16* __restrict__ I1,
             const __nv_bfloat16* __restrict__ I2,
             const float* __restrict__ b0p, const float* __restrict__ b1p, const float* __restrict__ b2p,
             float* __restrict__ C0, float* __restrict__ C1, float* __restrict__ C2,
             int Mrows, const float* __restrict__ resid, const float* __restrict__ skipv) {
    extern __shared__ char smem[];
    const __nv_bfloat16* img  = (blockIdx.y == 0) ? I0 : (blockIdx.y == 1 ? I1 : I2);
    const float*         bias = (blockIdx.y == 0) ? b0p : (blockIdx.y == 1 ? b1p : b2p);
    float*               C    = (blockIdx.y == 0) ? C0 : (blockIdx.y == 1 ? C1 : C2);

    int tid = threadIdx.x, lane = tid & 31, wid = tid >> 5;
    int r0 = blockIdx.x * 128;

    uint32_t sbase = smem_to_u32(smem);
    int warp_m = wid & 3, warp_n = wid >> 2;
    int gidq = lane >> 2, tidq = lane & 3;
    int mbase = warp_m * 32;
    int nbase = warp_n * 64;

    float acc[2][8][4];
#pragma unroll
    for (int mt = 0; mt < 2; mt++)
#pragma unroll
        for (int nt = 0; nt < 8; nt++)
#pragma unroll
            for (int j = 0; j < 4; j++) acc[mt][nt][j] = 0.f;

    uint32_t aAddr0 = sbase + GS_AHI + (uint32_t)(mbase + (lane & 15)) * AST2 + ((lane >> 4) * 16);
    uint32_t bAddr0 = sbase + GS_BHI + (uint32_t)(nbase + ((lane >> 4) * 8) + (lane & 7)) * AST2
                    + (((lane >> 3) & 1) * 16);

    int grow_s = r0 + (tid >> 1);
    bool ok_s = grow_s < Mrows;
    int half_s = tid & 1;

#pragma unroll
    for (int kc = 0; kc < 2; kc++) {
        for (int i = tid; i < 1024; i += 256) {
            int n = i >> 3, j = i & 7;
            cp_async16(sbase + GS_BHI + n * AST2 + j * 16,
                       img + n * 128 + kc * 64 + j * 8);
            cp_async16(sbase + GS_BLO + n * AST2 + j * 16,
                       img + 16384 + n * 128 + kc * 64 + j * 8);
        }
        cp_async_commit();
        {
            const float4* ap = (const float4*)(A + (size_t)grow_s * 128 + kc * 64 + half_s * 32);
            char* dhi = smem + GS_AHI + (tid >> 1) * AST2 + half_s * 64;
            char* dlo = smem + GS_ALO + (tid >> 1) * AST2 + half_s * 64;
#pragma unroll
            for (int c4 = 0; c4 < 8; c4++) {
                float4 v = ok_s ? ap[c4] : make_float4(0.f, 0.f, 0.f, 0.f);
                if (MODE == 1) {
                    v.x = gelu_f(v.x); v.y = gelu_f(v.y);
                    v.z = gelu_f(v.z); v.w = gelu_f(v.w);
                }
                __nv_bfloat16 h[4], l[4];
                h[0] = __float2bfloat16(v.x); l[0] = __float2bfloat16(v.x - __bfloat162float(h[0]));
                h[1] = __float2bfloat16(v.y); l[1] = __float2bfloat16(v.y - __bfloat162float(h[1]));
                h[2] = __float2bfloat16(v.z); l[2] = __float2bfloat16(v.z - __bfloat162float(h[2]));
                h[3] = __float2bfloat16(v.w); l[3] = __float2bfloat16(v.w - __bfloat162float(h[3]));
                *(uint2*)(dhi + c4 * 8) = *(uint2*)h;
                *(uint2*)(dlo + c4 * 8) = *(uint2*)l;
            }
        }
        cp_async_wait0();
        __syncthreads();

#pragma unroll
        for (int ks = 0; ks < 4; ks++) {
            uint32_t kb = ks * 32;
            uint32_t ah[2][4], al[2][4];
#pragma unroll
            for (int mt = 0; mt < 2; mt++) {
                uint32_t a0 = aAddr0 + (uint32_t)(mt * 16) * AST2 + kb;
                ldsm_x4(ah[mt], a0);
                ldsm_x4(al[mt], a0 + (GS_ALO - GS_AHI));
            }
            uint32_t bh[4][4], bl[4][4];
#pragma unroll
            for (int np = 0; np < 4; np++) {
                uint32_t b0 = bAddr0 + (uint32_t)(np * 16) * AST2 + kb;
                ldsm_x4(bh[np], b0);
                ldsm_x4(bl[np], b0 + (GS_BLO - GS_BHI));
            }
#pragma unroll
            for (int np = 0; np < 4; np++) {
#pragma unroll
                for (int half = 0; half < 2; half++) {
                    int nt = np * 2 + half;
                    uint32_t b0h = bh[np][half * 2], b1h = bh[np][half * 2 + 1];
                    uint32_t b0l = bl[np][half * 2], b1l = bl[np][half * 2 + 1];
                    mma16816(acc[0][nt], ah[0], b0h, b1h);
                    mma16816(acc[1][nt], ah[1], b0h, b1h);
                    mma16816(acc[0][nt], ah[0], b0l, b1l);
                    mma16816(acc[1][nt], ah[1], b0l, b1l);
                    mma16816(acc[0][nt], al[0], b0h, b1h);
                    mma16816(acc[1][nt], al[1], b0h, b1h);
                }
            }
        }
        __syncthreads();
    }

    float mix = 1.0f, omix = 0.0f;
    if (MODE == 1) {
        float s = *skipv;
        mix = 1.0f / (1.0f + expf(-s));
        omix = 1.0f - mix;
    }
#pragma unroll
    for (int mt = 0; mt < 2; mt++) {
        int rowA = r0 + mbase + mt * 16 + gidq;
        int rowB = rowA + 8;
#pragma unroll
        for (int nt = 0; nt < 8; nt++) {
            int col = nbase + nt * 8 + tidq * 2;
            float bx = bias[col], by = bias[col + 1];
            if (rowA < Mrows) {
                float2 o = make_float2(acc[mt][nt][0] + bx, acc[mt][nt][1] + by);
                if (MODE == 1) {
                    float2 old = *(const float2*)(resid + (size_t)rowA * 128 + col);
                    o.x = mix * o.x + omix * old.x;
                    o.y = mix * o.y + omix * old.y;
                }
                *(float2*)(C + (size_t)rowA * 128 + col) = o;
            }
            if (rowB < Mrows) {
                float2 o = make_float2(acc[mt][nt][2] + bx, acc[mt][nt][3] + by);
                if (MODE == 1) {
                    float2 old = *(const float2*)(resid + (size_t)rowB * 128 + col);
                    o.x = mix * o.x + omix * old.x;
                    o.y = mix * o.y + omix * old.y;
                }
                *(float2*)(C + (size_t)rowB * 128 + col) = o;
            }
        }
    }
}

// ================= CSR build =================
__global__ void hist_kernel(const int* __restrict__ ei, const int* __restrict__ et,
                            int* __restrict__ counts) {
    int e = blockIdx.x * blockDim.x + threadIdx.x;
    if (e >= EE) return;
    int dst = ei[EE + e], r = et[e];
    atomicAdd(&counts[dst * 4 + r], 1);
}

__global__ __launch_bounds__(1024)
void scan_pass1(const int* __restrict__ counts, int* __restrict__ bsum) {
    __shared__ int swarp[32];
    int b = blockIdx.x, t = threadIdx.x;
    int base = b * SCAN_CHUNK + t * 4;
    int tot = 0;
#pragma unroll
    for (int j = 0; j < 4; j++) {
        int idx = base + j;
        tot += (idx < NSEG) ? counts[idx] : 0;
    }
#pragma unroll
    for (int d = 16; d; d >>= 1) tot += __shfl_xor_sync(0xffffffffu, tot, d);
    if ((t & 31) == 0) swarp[t >> 5] = tot;
    __syncthreads();
    if (t < 32) {
        int v = swarp[t];
#pragma unroll
        for (int d = 16; d; d >>= 1) v += __shfl_xor_sync(0xffffffffu, v, d);
        if (t == 0) bsum[b] = v;
    }
}

__global__ void scan_pass2(const int* __restrict__ bsum, int* __restrict__ boff,
                           int* __restrict__ offs) {
    if (threadIdx.x == 0 && blockIdx.x == 0) {
        int run = 0;
        for (int i = 0; i < SCAN_B; i++) { boff[i] = run; run += bsum[i]; }
        offs[NSEG] = run;
    }
}

__global__ __launch_bounds__(1024)
void scan_pass3(const int* __restrict__ counts, const int* __restrict__ boff,
                int* __restrict__ offs, int* __restrict__ cursor) {
    __shared__ int swarp[32];
    int b = blockIdx.x, t = threadIdx.x;
    int base = b * SCAN_CHUNK + t * 4;
    int c[4]; int tot = 0;
#pragma unroll
    for (int j = 0; j < 4; j++) {
        int idx = base + j;
        c[j] = (idx < NSEG) ? counts[idx] : 0;
        tot += c[j];
    }
    int lane = t & 31, w = t >> 5;
    int v = tot;
#pragma unroll
    for (int d = 1; d < 32; d <<= 1) {
        int n = __shfl_up_sync(0xffffffffu, v, d);
        if (lane >= d) v += n;
    }
    if (lane == 31) swarp[w] = v;
    __syncthreads();
    if (w == 0) {
        int sv = swarp[lane];
#pragma unroll
        for (int d = 1; d < 32; d <<= 1) {
            int n = __shfl_up_sync(0xffffffffu, sv, d);
            if (lane >= d) sv += n;
        }
        swarp[lane] = sv;
    }
    __syncthreads();
    int excl = v - tot + ((w > 0) ? swarp[w - 1] : 0) + boff[b];
#pragma unroll
    for (int j = 0; j < 4; j++) {
        int idx = base + j;
        if (idx < NSEG) { offs[idx] = excl; cursor[idx] = excl; }
        excl += c[j];
    }
}

__global__ void scatter_kernel(const int* __restrict__ ei, const int* __restrict__ et,
                               int* __restrict__ cursor, int* __restrict__ ssrc) {
    int e = blockIdx.x * blockDim.x + threadIdx.x;
    if (e >= EE) return;
    int src = ei[e], dst = ei[EE + e], r = et[e];
    int pos = atomicAdd(&cursor[dst * 4 + r], 1);
    ssrc[pos] = src;
}

// ================= q transform: qr[n][r][h][d] = sum_e a_rel[r][h][d][e] * q[n][h][e] =================
// f32x2 paired over node pairs.
__global__ __launch_bounds__(512)
void q_transform_kernel(const float* __restrict__ qin, const float* __restrict__ a_rel,
                        float* __restrict__ qr, int n) {
    __shared__ __align__(16) float qsh[256];   // interleaved pair (q[n0][c], q[n1][c])
    int tid = threadIdx.x;
    int h = (tid >> 5) & 3;
    u64 w2[32];
    {
        const float* ab = a_rel + (size_t)tid * 32;   // tid = (r*4+h)*32 + d -> row [d][e] contiguous
#pragma unroll
        for (int e = 0; e < 32; e++) w2[e] = packdup(ab[e]);
    }
    for (int n0 = blockIdx.x * 2; n0 < n; n0 += gridDim.x * 2) {
        __syncthreads();
        if (tid < 256) {
            int c = tid >> 1, which = tid & 1;
            int node = n0 + which;
            qsh[tid] = (node < n) ? qin[(size_t)node * 128 + c] : 0.f;
        }
        __syncthreads();
        u64 acc = 0ull;
        const u64* qp = (const u64*)qsh + h * 32;
#pragma unroll
        for (int e = 0; e < 32; e++) fma2(acc, qp[e], w2[e]);
        float a0, a1;
        unpack2(acc, a0, a1);
        qr[(size_t)n0 * 512 + tid] = a0;
        if (n0 + 1 < n) qr[(size_t)(n0 + 1) * 512 + tid] = a1;
    }
}

// ================= fused edge attention v3: raw k/v gathers + per-segment M^T =================
// Lane l: head h = l>>3, group idx l0 = l&7; owns d-dims (and e-dims) 4*l0..4*l0+3.
__global__ __launch_bounds__(256)
void edge_attn_kernel(const float* __restrict__ qr, const int* __restrict__ offs,
                      const int* __restrict__ ssrc, const float* __restrict__ p_rel,
                      const float* __restrict__ m_rel, float* __restrict__ attn) {
    extern __shared__ float msh[];   // 16384 floats = 64KB : m_rel[r][h][d][e]
    for (int i = threadIdx.x; i < 4096; i += 256)
        ((float4*)msh)[i] = ((const float4*)m_rel)[i];
    __syncthreads();

    int lane = threadIdx.x & 31;
    int h = lane >> 3, l0 = lane & 7;
    int gwarp = blockIdx.x * 8 + ((int)threadIdx.x >> 5);
    const float SCALE = 0.17677669529663687f;

    for (int node = gwarp; node < NN; node += EA_WARPS) {
        float4 o4 = make_float4(0.f, 0.f, 0.f, 0.f);
        int obase = node * 4;
#pragma unroll
        for (int r = 0; r < 4; r++) {
            int s = offs[obase + r], e = offs[obase + r + 1];
            if (s >= e) continue;
            float4 q4 = *(const float4*)(qr + (size_t)node * 512 + r * 128 + lane * 4);
            float pr = p_rel[r * 4 + h] * SCALE;
            float m = -INFINITY, z = 0.f;
            float4 a4 = make_float4(0.f, 0.f, 0.f, 0.f);

            int src0 = __ldg(&ssrc[s]);
            float4 k_cur = *(const float4*)(g_k + (size_t)src0 * 128 + lane * 4);
            float4 v_cur = *(const float4*)(g_v + (size_t)src0 * 128 + lane * 4);

            for (int pos = s; pos < e; pos++) {
                float4 k4 = k_cur, v4 = v_cur;
                if (pos + 1 < e) {
                    int srcn = __ldg(&ssrc[pos + 1]);
                    k_cur = *(const float4*)(g_k + (size_t)srcn * 128 + lane * 4);
                    v_cur = *(const float4*)(g_v + (size_t)srcn * 128 + lane * 4);
                }
                float sc = q4.x * k4.x + q4.y * k4.y + q4.z * k4.z + q4.w * k4.w;
                sc += __shfl_xor_sync(0xffffffffu, sc, 1);
                sc += __shfl_xor_sync(0xffffffffu, sc, 2);
                sc += __shfl_xor_sync(0xffffffffu, sc, 4);
                sc *= pr;
                float nm = fmaxf(m, sc);
                float eo = __expf(m - nm);
                float es = __expf(sc - nm);
                z = z * eo + es;
                a4.x = a4.x * eo + es * v4.x;
                a4.y = a4.y * eo + es * v4.y;
                a4.z = a4.z * eo + es * v4.z;
                a4.w = a4.w * eo + es * v4.w;
                m = nm;
            }
            float iz = 1.0f / z;
            float w0 = a4.x * iz, w1 = a4.y * iz, w2 = a4.z * iz, w3 = a4.w * iz;

            // o_e += sum_d M[r][h][d][e] * w_d  via 8-lane butterfly
            const float* Mb = msh + (r * 4 + h) * 1024;
            int eb = l0 * 4;
#pragma unroll
            for (int j = 0; j < 8; j++) {
                int gsrc = (l0 + j) & 7;
                int srclane = (h << 3) | gsrc;
                float wa = __shfl_sync(0xffffffffu, w0, srclane);
                float wb = __shfl_sync(0xffffffffu, w1, srclane);
                float wc = __shfl_sync(0xffffffffu, w2, srclane);
                float wd = __shfl_sync(0xffffffffu, w3, srclane);
                const float* Mr = Mb + (gsrc * 4) * 32 + eb;
                float4 m0 = *(const float4*)(Mr);
                float4 m1 = *(const float4*)(Mr + 32);
                float4 m2 = *(const float4*)(Mr + 64);
                float4 m3 = *(const float4*)(Mr + 96);
                o4.x += wa * m0.x + wb * m1.x + wc * m2.x + wd * m3.x;
                o4.y += wa * m0.y + wb * m1.y + wc * m2.y + wd * m3.y;
                o4.z += wa * m0.z + wb * m1.z + wc * m2.z + wd * m3.z;
                o4.w += wa * m0.w + wb * m1.w + wc * m2.w + wd * m3.w;
            }
        }
        *(float4*)(attn + (size_t)node * 128 + lane * 4) = o4;
    }
}

// ---------------- BatchNorm ----------------
__global__ __launch_bounds__(512)
void bn_stats_kernel(const float* __restrict__ h, float* __restrict__ stats, int n) {
    __shared__ float4 s_sum[16][32];
    __shared__ float4 s_sq[16][32];
    int tid = threadIdx.x;
    int c4 = tid & 31;
    int rg = tid >> 5;
    float4 sum = make_float4(0.f, 0.f, 0.f, 0.f);
    float4 sq  = make_float4(0.f, 0.f, 0.f, 0.f);
    for (int r = blockIdx.x * 16 + rg; r < n; r += gridDim.x * 16) {
        float4 v = *(const float4*)(h + (size_t)r * 128 + c4 * 4);
        sum.x += v.x; sum.y += v.y; sum.z += v.z; sum.w += v.w;
        sq.x += v.x * v.x; sq.y += v.y * v.y; sq.z += v.z * v.z; sq.w += v.w * v.w;
    }
    s_sum[rg][c4] = sum; s_sq[rg][c4] = sq;
    __syncthreads();
#pragma unroll
    for (int step = 8; step >= 1; step >>= 1) {
        if (rg < step) {
            float4 a = s_sum[rg][c4], b = s_sum[rg + step][c4];
            a.x += b.x; a.y += b.y; a.z += b.z; a.w += b.w;
            s_sum[rg][c4] = a;
            float4 e = s_sq[rg][c4], f = s_sq[rg + step][c4];
            e.x += f.x; e.y += f.y; e.z += f.z; e.w += f.w;
            s_sq[rg][c4] = e;
        }
        __syncthreads();
    }
    if (rg == 0) {
        float4 a = s_sum[0][c4], e = s_sq[0][c4];
        atomicAdd(&stats[c4 * 4 + 0], a.x);
        atomicAdd(&stats[c4 * 4 + 1], a.y);
        atomicAdd(&stats[c4 * 4 + 2], a.z);
        atomicAdd(&stats[c4 * 4 + 3], a.w);
        atomicAdd(&stats[128 + c4 * 4 + 0], e.x);
        atomicAdd(&stats[128 + c4 * 4 + 1], e.y);
        atomicAdd(&stats[128 + c4 * 4 + 2], e.z);
        atomicAdd(&stats[128 + c4 * 4 + 3], e.w);
    }
}

__global__ void bn_apply_kernel(float* __restrict__ h, const float* __restrict__ stats,
                                const float* __restrict__ gamma, const float* __restrict__ beta,
                                int n) {
    int i = blockIdx.x * blockDim.x + threadIdx.x;
    if (i >= n * 32) return;
    int c4 = (i & 31) * 4;
    float4 hv = reinterpret_cast<float4*>(h)[i];
    float4 mu = *reinterpret_cast<const float4*>(stats + c4);
    float4 sg = *reinterpret_cast<const float4*>(stats + 128 + c4);
    float4 ga = *reinterpret_cast<const float4*>(gamma + c4);
    float4 be = *reinterpret_cast<const float4*>(beta + c4);
    const float inv = 1.0f / (float)NN;
    float m0 = mu.x * inv, m1 = mu.y * inv, m2 = mu.z * inv, m3 = mu.w * inv;
    hv.x = (hv.x - m0) * rsqrtf(sg.x * inv - m0 * m0 + 1e-5f) * ga.x + be.x;
    hv.y = (hv.y - m1) * rsqrtf(sg.y * inv - m1 * m1 + 1e-5f) * ga.y + be.y;
    hv.z = (hv.z - m2) * rsqrtf(sg.z * inv - m2 * m2 + 1e-5f) * ga.z + be.z;
    hv.w = (hv.w - m3) * rsqrtf(sg.w * inv - m3 * m3 + 1e-5f) * ga.w + be.w;
    reinterpret_cast<float4*>(h)[i] = hv;
}

// ---------------- gather ----------------
__global__ void gather_kernel(const int* __restrict__ idx, const float* __restrict__ h,
                              float* __restrict__ out) {
    int gid = blockIdx.x * blockDim.x + threadIdx.x;
    if (gid >= MMOUT * 32) return;
    int m = gid >> 5, c4 = gid & 31;
    reinterpret_cast<float4*>(out)[(size_t)m * 32 + c4] =
        reinterpret_cast<const float4*>(h + (size_t)idx[m] * 128)[c4];
}

// ---------------- launch ----------------
extern "C" void kernel_launch(void* const* d_in, const int* in_sizes, int n_in,
                              void* d_out, int out_size) {
    const float* x        = (const float*)d_in[0];
    const float* proj_w   = (const float*)d_in[1];
    const float* proj_b   = (const float*)d_in[2];
    const float* bn_gamma = (const float*)d_in[3];
    const float* bn_beta  = (const float*)d_in[4];
    const float* q_w      = (const float*)d_in[5];
    const float* q_b      = (const float*)d_in[6];
    const float* k_w      = (const float*)d_in[7];
    const float* k_b      = (const float*)d_in[8];
    const float* v_w      = (const float*)d_in[9];
    const float* v_b      = (const float*)d_in[10];
    const float* a_w      = (const float*)d_in[11];
    const float* a_b      = (const float*)d_in[12];
    const float* skip     = (const float*)d_in[13];
    const float* a_rel    = (const float*)d_in[14];
    const float* m_rel    = (const float*)d_in[15];
    const float* p_rel    = (const float*)d_in[16];
    const int*   edge_idx = (const int*)d_in[17];
    const int*   edge_typ = (const int*)d_in[18];
    const int*   idx      = (const int*)d_in[19];
    float*       out      = (float*)d_out;

    float *p_h, *p_q, *p_k, *p_v, *p_qr, *p_attn, *p_stats;
    int *p_counts, *p_offs, *p_cursor, *p_bsum, *p_boff, *p_ssrc;
    __nv_bfloat16* p_wimg;
    cudaGetSymbolAddress((void**)&p_h, g_h);
    cudaGetSymbolAddress((void**)&p_q, g_q);
    cudaGetSymbolAddress((void**)&p_k, g_k);
    cudaGetSymbolAddress((void**)&p_v, g_v);
    cudaGetSymbolAddress((void**)&p_qr, g_qr);
    cudaGetSymbolAddress((void**)&p_attn, g_attn);
    cudaGetSymbolAddress((void**)&p_stats, g_stats);
    cudaGetSymbolAddress((void**)&p_counts, g_counts);
    cudaGetSymbolAddress((void**)&p_offs, g_offs);
    cudaGetSymbolAddress((void**)&p_cursor, g_cursor);
    cudaGetSymbolAddress((void**)&p_bsum, g_bsum);
    cudaGetSymbolAddress((void**)&p_boff, g_boff);
    cudaGetSymbolAddress((void**)&p_ssrc, g_ssrc);
    cudaGetSymbolAddress((void**)&p_wimg, g_wimg);

    cudaFuncSetAttribute(gemm_tc<0>, cudaFuncAttributeMaxDynamicSharedMemorySize, GS_TOTAL);
    cudaFuncSetAttribute(gemm_tc<1>, cudaFuncAttributeMaxDynamicSharedMemorySize, GS_TOTAL);
    cudaFuncSetAttribute(edge_attn_kernel, cudaFuncAttributeMaxDynamicSharedMemorySize, 65536);

    const int gemmGrid = (NN + 127) / 128;   // 391
    const int eBlocks = (EE + 255) / 256;

    const __nv_bfloat16* imgP  = p_wimg;
    const __nv_bfloat16* imgQ0 = p_wimg + 1 * 32768;
    const __nv_bfloat16* imgQ1 = p_wimg + 2 * 32768;
    const __nv_bfloat16* imgK0 = p_wimg + 3 * 32768;
    const __nv_bfloat16* imgK1 = p_wimg + 4 * 32768;
    const __nv_bfloat16* imgV0 = p_wimg + 5 * 32768;
    const __nv_bfloat16* imgV1 = p_wimg + 6 * 32768;
    const __nv_bfloat16* imgA0 = p_wimg + 7 * 32768;
    const __nv_bfloat16* imgA1 = p_wimg + 8 * 32768;

    // launches 0-3 (gemm proj in profiled slot = launch index 3)
    fill_zero_kernel<<<1, 256>>>((unsigned*)p_stats, 2 * HIDN);
    wprep_kernel<<<9, 128>>>(proj_w, q_w, k_w, v_w, a_w);
    fill_zero_kernel<<<(NSEG + 255) / 256, 256>>>((unsigned*)p_counts, NSEG);
    gemm_tc<0><<<dim3(gemmGrid, 1), 256, GS_TOTAL>>>(x, imgP, imgP, imgP,
                                                     proj_b, proj_b, proj_b,
                                                     p_h, p_h, p_h, NN, nullptr, nullptr);

    // ---- CSR build (independent of h) ----
    hist_kernel<<<eBlocks, 256>>>(edge_idx, edge_typ, p_counts);
    scan_pass1<<<SCAN_B, 1024>>>(p_counts, p_bsum);
    scan_pass2<<<1, 32>>>(p_bsum, p_boff, p_offs);
    scan_pass3<<<SCAN_B, 1024>>>(p_counts, p_boff, p_offs, p_cursor);
    scatter_kernel<<<eBlocks, 256>>>(edge_idx, edge_typ, p_cursor, p_ssrc);

    // ---- BN ----
    bn_stats_kernel<<<592, 512>>>(p_h, p_stats, NN);
    bn_apply_kernel<<<(NN * 32 + 255) / 256, 256>>>(p_h, p_stats, bn_gamma, bn_beta, NN);

    // layer 0 fused QKV
    gemm_tc<0><<<dim3(gemmGrid, 3), 256, GS_TOTAL>>>(p_h, imgQ0, imgK0, imgV0,
                                                     q_b, k_b, v_b,
                                                     p_q, p_k, p_v, NN, nullptr, nullptr);

    for (int l = 0; l < LLAY; l++) {
        const float* abl = a_b + (size_t)l * 128;
        const float* arl = a_rel + (size_t)l * RR * HH * DDIM * DDIM;
        const float* mrl = m_rel + (size_t)l * RR * HH * DDIM * DDIM;
        const float* prl = p_rel + (size_t)l * RR * HH;
        const float* skl = skip + l;
        const __nv_bfloat16* imgA = (l == 0) ? imgA0 : imgA1;

        if (l > 0) {
            gemm_tc<0><<<dim3(gemmGrid, 3), 256, GS_TOTAL>>>(
                p_h, imgQ1, imgK1, imgV1,
                q_b + 128, k_b + 128, v_b + 128,
                p_q, p_k, p_v, NN, nullptr, nullptr);
        }

        q_transform_kernel<<<592, 512>>>(p_q, arl, p_qr, NN);

        edge_attn_kernel<<<EA_BLOCKS, 256, 65536>>>(p_qr, p_offs, p_ssrc, prl, mrl, p_attn);

        gemm_tc<1><<<dim3(gemmGrid, 1), 256, GS_TOTAL>>>(p_attn, imgA, imgA, imgA,
                                                         abl, abl, abl,
                                                         p_h, p_h, p_h, NN, p_h, skl);
    }

    gather_kernel<<<(MMOUT * 32 + 255) / 256, 256>>>(idx, p_h, out);
}

// round 13
// speedup vs baseline: 1.1278x; 1.1278x over previous
#include <cuda_runtime.h>
#include <cuda_bf16.h>
#include <math.h>
#include <cstdint>

#define NN   50000
#define EE   600000
#define HIDN 128
#define HH   4
#define DDIM 32
#define RR   4
#define LLAY 2
#define MMOUT 10000
#define NSEG (NN * RR)
#define SCAN_CHUNK 4096
#define SCAN_B ((NSEG + SCAN_CHUNK - 1) / SCAN_CHUNK)   // 49
#define EA_BLOCKS 296
#define EA_WPB 16
#define EA_WARPS (EA_BLOCKS * EA_WPB)   // 4736

typedef unsigned long long u64;

// ---------------- scratch ----------------
__device__ float g_h[NN * HIDN];
__device__ float g_q[NN * HIDN];
__device__ float g_k[NN * HIDN];
__device__ float g_v[NN * HIDN];
__device__ float g_qr[NN * RR * HIDN];   // A_r^T q : [n][r][h][d]
__device__ float g_attn[NN * HIDN];
__device__ float g_stats[2 * HIDN];
__device__ int   g_counts[NSEG];
__device__ int   g_offs[NSEG + 1];
__device__ int   g_cursor[NSEG];
__device__ int   g_bsum[SCAN_B];
__device__ int   g_boff[SCAN_B];
__device__ int   g_ssrc[EE];
// transposed bf16 hi/lo weight images: 9 matrices x (hi[n][k] 16384 + lo[n][k] 16384)
__device__ __nv_bfloat16 g_wimg[9 * 32768];

// ---------------- f32x2 helpers ----------------
__device__ __forceinline__ void fma2(u64& d, u64 a, u64 b) {
    asm("fma.rn.f32x2 %0, %1, %2, %0;" : "+l"(d) : "l"(a), "l"(b));
}
__device__ __forceinline__ u64 packdup(float s) {
    u64 r; asm("mov.b64 %0, {%1, %1};" : "=l"(r) : "f"(s)); return r;
}
__device__ __forceinline__ void unpack2(u64 v, float& lo, float& hi) {
    asm("mov.b64 {%0, %1}, %2;" : "=f"(lo), "=f"(hi) : "l"(v));
}
__device__ __forceinline__ float gelu_f(float x) {
    return 0.5f * x * (1.0f + erff(x * 0.7071067811865475f));
}

// ---------------- mma / ldmatrix / cp.async helpers ----------------
__device__ __forceinline__ void mma16816(float* c, const uint32_t* a, uint32_t b0, uint32_t b1) {
    asm volatile(
        "mma.sync.aligned.m16n8k16.row.col.f32.bf16.bf16.f32 "
        "{%0,%1,%2,%3}, {%4,%5,%6,%7}, {%8,%9}, {%0,%1,%2,%3};"
        : "+f"(c[0]), "+f"(c[1]), "+f"(c[2]), "+f"(c[3])
        : "r"(a[0]), "r"(a[1]), "r"(a[2]), "r"(a[3]), "r"(b0), "r"(b1));
}
__device__ __forceinline__ void ldsm_x4(uint32_t* r, uint32_t addr) {
    asm volatile("ldmatrix.sync.aligned.m8n8.x4.shared.b16 {%0,%1,%2,%3}, [%4];"
                 : "=r"(r[0]), "=r"(r[1]), "=r"(r[2]), "=r"(r[3]) : "r"(addr));
}
__device__ __forceinline__ uint32_t smem_to_u32(const void* p) {
    uint32_t a;
    asm("{ .reg .u64 t; cvta.to.shared.u64 t, %1; cvt.u32.u64 %0, t; }" : "=r"(a) : "l"(p));
    return a;
}
__device__ __forceinline__ void cp_async16(uint32_t dst, const void* src) {
    asm volatile("cp.async.cg.shared.global [%0], [%1], 16;" :: "r"(dst), "l"(src));
}
__device__ __forceinline__ void cp_async_commit() {
    asm volatile("cp.async.commit_group;" ::: "memory");
}
__device__ __forceinline__ void cp_async_wait0() {
    asm volatile("cp.async.wait_group 0;" ::: "memory");
}

// K-chunked GEMM smem layout
#define AST2 144
#define GS_AHI 0
#define GS_ALO (128 * AST2)
#define GS_BHI (2 * 128 * AST2)
#define GS_BLO (3 * 128 * AST2)
#define GS_TOTAL (4 * 128 * AST2)    // 73728

// ---------------- fill ----------------
__global__ void fill_zero_kernel(unsigned* __restrict__ p, int n) {
    int i = blockIdx.x * blockDim.x + threadIdx.x;
    if (i < n) p[i] = 0u;
}

// ================= weight prep =================
__global__ __launch_bounds__(128)
void wprep_kernel(const float* __restrict__ proj_w, const float* __restrict__ q_w,
                  const float* __restrict__ k_w, const float* __restrict__ v_w,
                  const float* __restrict__ a_w) {
    __shared__ float ws[64 * 128];
    int b = blockIdx.x, tid = threadIdx.x;
    const float* W;
    if (b == 0)      W = proj_w;
    else if (b <= 2) W = q_w + (size_t)(b - 1) * 16384;
    else if (b <= 4) W = k_w + (size_t)(b - 3) * 16384;
    else if (b <= 6) W = v_w + (size_t)(b - 5) * 16384;
    else             W = a_w + (size_t)(b - 7) * 16384;
    __nv_bfloat16* imgh = g_wimg + (size_t)b * 32768;
    __nv_bfloat16* imgl = imgh + 16384;

    for (int chunk = 0; chunk < 2; chunk++) {
        __syncthreads();
        for (int i = tid; i < 64 * 32; i += 128)
            ((float4*)ws)[i] = ((const float4*)(W + chunk * 64 * 128))[i];
        __syncthreads();
        int n = tid;
#pragma unroll
        for (int kk = 0; kk < 64; kk += 4) {
            __nv_bfloat16 h4[4], l4[4];
#pragma unroll
            for (int t = 0; t < 4; t++) {
                float v = ws[(kk + t) * 128 + n];
                __nv_bfloat16 hh = __float2bfloat16(v);
                h4[t] = hh;
                l4[t] = __float2bfloat16(v - __bfloat162float(hh));
            }
            *(uint2*)(imgh + n * 128 + chunk * 64 + kk) = *(uint2*)h4;
            *(uint2*)(imgl + n * 128 + chunk * 64 + kk) = *(uint2*)l4;
        }
    }
}

// ================= tensor-core GEMM (K-chunked, cp.async B staging) =================
template <int MODE>
__global__ __launch_bounds__(256, 2)
void gemm_tc(const float* __restrict__ A,
             const __nv_bfloat16* __restrict__ I0, const __nv_bfloat16* __restrict__ I1,
             const __nv_bfloat16* __restrict__ I2,
             const float* __restrict__ b0p, const float* __restrict__ b1p, const float* __restrict__ b2p,
             float* __restrict__ C0, float* __restrict__ C1, float* __restrict__ C2,
             int Mrows, const float* __restrict__ resid, const float* __restrict__ skipv) {
    extern __shared__ char smem[];
    const __nv_bfloat16* img  = (blockIdx.y == 0) ? I0 : (blockIdx.y == 1 ? I1 : I2);
    const float*         bias = (blockIdx.y == 0) ? b0p : (blockIdx.y == 1 ? b1p : b2p);
    float*               C    = (blockIdx.y == 0) ? C0 : (blockIdx.y == 1 ? C1 : C2);

    int tid = threadIdx.x, lane = tid & 31, wid = tid >> 5;
    int r0 = blockIdx.x * 128;

    uint32_t sbase = smem_to_u32(smem);
    int warp_m = wid & 3, warp_n = wid >> 2;
    int gidq = lane >> 2, tidq = lane & 3;
    int mbase = warp_m * 32;
    int nbase = warp_n * 64;

    float acc[2][8][4];
#pragma unroll
    for (int mt = 0; mt < 2; mt++)
#pragma unroll
        for (int nt = 0; nt < 8; nt++)
#pragma unroll
            for (int j = 0; j < 4; j++) acc[mt][nt][j] = 0.f;

    uint32_t aAddr0 = sbase + GS_AHI + (uint32_t)(mbase + (lane & 15)) * AST2 + ((lane >> 4) * 16);
    uint32_t bAddr0 = sbase + GS_BHI + (uint32_t)(nbase + ((lane >> 4) * 8) + (lane & 7)) * AST2
                    + (((lane >> 3) & 1) * 16);

    int grow_s = r0 + (tid >> 1);
    bool ok_s = grow_s < Mrows;
    int half_s = tid & 1;

#pragma unroll
    for (int kc = 0; kc < 2; kc++) {
        for (int i = tid; i < 1024; i += 256) {
            int n = i >> 3, j = i & 7;
            cp_async16(sbase + GS_BHI + n * AST2 + j * 16,
                       img + n * 128 + kc * 64 + j * 8);
            cp_async16(sbase + GS_BLO + n * AST2 + j * 16,
                       img + 16384 + n * 128 + kc * 64 + j * 8);
        }
        cp_async_commit();
        {
            const float4* ap = (const float4*)(A + (size_t)grow_s * 128 + kc * 64 + half_s * 32);
            char* dhi = smem + GS_AHI + (tid >> 1) * AST2 + half_s * 64;
            char* dlo = smem + GS_ALO + (tid >> 1) * AST2 + half_s * 64;
#pragma unroll
            for (int c4 = 0; c4 < 8; c4++) {
                float4 v = ok_s ? ap[c4] : make_float4(0.f, 0.f, 0.f, 0.f);
                if (MODE == 1) {
                    v.x = gelu_f(v.x); v.y = gelu_f(v.y);
                    v.z = gelu_f(v.z); v.w = gelu_f(v.w);
                }
                __nv_bfloat16 h[4], l[4];
                h[0] = __float2bfloat16(v.x); l[0] = __float2bfloat16(v.x - __bfloat162float(h[0]));
                h[1] = __float2bfloat16(v.y); l[1] = __float2bfloat16(v.y - __bfloat162float(h[1]));
                h[2] = __float2bfloat16(v.z); l[2] = __float2bfloat16(v.z - __bfloat162float(h[2]));
                h[3] = __float2bfloat16(v.w); l[3] = __float2bfloat16(v.w - __bfloat162float(h[3]));
                *(uint2*)(dhi + c4 * 8) = *(uint2*)h;
                *(uint2*)(dlo + c4 * 8) = *(uint2*)l;
            }
        }
        cp_async_wait0();
        __syncthreads();

#pragma unroll
        for (int ks = 0; ks < 4; ks++) {
            uint32_t kb = ks * 32;
            uint32_t ah[2][4], al[2][4];
#pragma unroll
            for (int mt = 0; mt < 2; mt++) {
                uint32_t a0 = aAddr0 + (uint32_t)(mt * 16) * AST2 + kb;
                ldsm_x4(ah[mt], a0);
                ldsm_x4(al[mt], a0 + (GS_ALO - GS_AHI));
            }
            uint32_t bh[4][4], bl[4][4];
#pragma unroll
            for (int np = 0; np < 4; np++) {
                uint32_t b0 = bAddr0 + (uint32_t)(np * 16) * AST2 + kb;
                ldsm_x4(bh[np], b0);
                ldsm_x4(bl[np], b0 + (GS_BLO - GS_BHI));
            }
#pragma unroll
            for (int np = 0; np < 4; np++) {
#pragma unroll
                for (int half = 0; half < 2; half++) {
                    int nt = np * 2 + half;
                    uint32_t b0h = bh[np][half * 2], b1h = bh[np][half * 2 + 1];
                    uint32_t b0l = bl[np][half * 2], b1l = bl[np][half * 2 + 1];
                    mma16816(acc[0][nt], ah[0], b0h, b1h);
                    mma16816(acc[1][nt], ah[1], b0h, b1h);
                    mma16816(acc[0][nt], ah[0], b0l, b1l);
                    mma16816(acc[1][nt], ah[1], b0l, b1l);
                    mma16816(acc[0][nt], al[0], b0h, b1h);
                    mma16816(acc[1][nt], al[1], b0h, b1h);
                }
            }
        }
        __syncthreads();
    }

    float mix = 1.0f, omix = 0.0f;
    if (MODE == 1) {
        float s = *skipv;
        mix = 1.0f / (1.0f + expf(-s));
        omix = 1.0f - mix;
    }
#pragma unroll
    for (int mt = 0; mt < 2; mt++) {
        int rowA = r0 + mbase + mt * 16 + gidq;
        int rowB = rowA + 8;
#pragma unroll
        for (int nt = 0; nt < 8; nt++) {
            int col = nbase + nt * 8 + tidq * 2;
            float bx = bias[col], by = bias[col + 1];
            if (rowA < Mrows) {
                float2 o = make_float2(acc[mt][nt][0] + bx, acc[mt][nt][1] + by);
                if (MODE == 1) {
                    float2 old = *(const float2*)(resid + (size_t)rowA * 128 + col);
                    o.x = mix * o.x + omix * old.x;
                    o.y = mix * o.y + omix * old.y;
                }
                *(float2*)(C + (size_t)rowA * 128 + col) = o;
            }
            if (rowB < Mrows) {
                float2 o = make_float2(acc[mt][nt][2] + bx, acc[mt][nt][3] + by);
                if (MODE == 1) {
                    float2 old = *(const float2*)(resid + (size_t)rowB * 128 + col);
                    o.x = mix * o.x + omix * old.x;
                    o.y = mix * o.y + omix * old.y;
                }
                *(float2*)(C + (size_t)rowB * 128 + col) = o;
            }
        }
    }
}

// ================= CSR build =================
__global__ void hist_kernel(const int* __restrict__ ei, const int* __restrict__ et,
                            int* __restrict__ counts) {
    int e = blockIdx.x * blockDim.x + threadIdx.x;
    if (e >= EE) return;
    int dst = ei[EE + e], r = et[e];
    atomicAdd(&counts[dst * 4 + r], 1);
}

__global__ __launch_bounds__(1024)
void scan_pass1(const int* __restrict__ counts, int* __restrict__ bsum) {
    __shared__ int swarp[32];
    int b = blockIdx.x, t = threadIdx.x;
    int base = b * SCAN_CHUNK + t * 4;
    int tot = 0;
#pragma unroll
    for (int j = 0; j < 4; j++) {
        int idx = base + j;
        tot += (idx < NSEG) ? counts[idx] : 0;
    }
#pragma unroll
    for (int d = 16; d; d >>= 1) tot += __shfl_xor_sync(0xffffffffu, tot, d);
    if ((t & 31) == 0) swarp[t >> 5] = tot;
    __syncthreads();
    if (t < 32) {
        int v = swarp[t];
#pragma unroll
        for (int d = 16; d; d >>= 1) v += __shfl_xor_sync(0xffffffffu, v, d);
        if (t == 0) bsum[b] = v;
    }
}

__global__ void scan_pass2(const int* __restrict__ bsum, int* __restrict__ boff,
                           int* __restrict__ offs) {
    if (threadIdx.x == 0 && blockIdx.x == 0) {
        int run = 0;
        for (int i = 0; i < SCAN_B; i++) { boff[i] = run; run += bsum[i]; }
        offs[NSEG] = run;
    }
}

__global__ __launch_bounds__(1024)
void scan_pass3(const int* __restrict__ counts, const int* __restrict__ boff,
                int* __restrict__ offs, int* __restrict__ cursor) {
    __shared__ int swarp[32];
    int b = blockIdx.x, t = threadIdx.x;
    int base = b * SCAN_CHUNK + t * 4;
    int c[4]; int tot = 0;
#pragma unroll
    for (int j = 0; j < 4; j++) {
        int idx = base + j;
        c[j] = (idx < NSEG) ? counts[idx] : 0;
        tot += c[j];
    }
    int lane = t & 31, w = t >> 5;
    int v = tot;
#pragma unroll
    for (int d = 1; d < 32; d <<= 1) {
        int n = __shfl_up_sync(0xffffffffu, v, d);
        if (lane >= d) v += n;
    }
    if (lane == 31) swarp[w] = v;
    __syncthreads();
    if (w == 0) {
        int sv = swarp[lane];
#pragma unroll
        for (int d = 1; d < 32; d <<= 1) {
            int n = __shfl_up_sync(0xffffffffu, sv, d);
            if (lane >= d) sv += n;
        }
        swarp[lane] = sv;
    }
    __syncthreads();
    int excl = v - tot + ((w > 0) ? swarp[w - 1] : 0) + boff[b];
#pragma unroll
    for (int j = 0; j < 4; j++) {
        int idx = base + j;
        if (idx < NSEG) { offs[idx] = excl; cursor[idx] = excl; }
        excl += c[j];
    }
}

__global__ void scatter_kernel(const int* __restrict__ ei, const int* __restrict__ et,
                               int* __restrict__ cursor, int* __restrict__ ssrc) {
    int e = blockIdx.x * blockDim.x + threadIdx.x;
    if (e >= EE) return;
    int src = ei[e], dst = ei[EE + e], r = et[e];
    int pos = atomicAdd(&cursor[dst * 4 + r], 1);
    ssrc[pos] = src;
}

// ================= q transform: qr[n][r][h][d] = sum_e a_rel[r][h][d][e] * q[n][h][e] =================
__global__ __launch_bounds__(512)
void q_transform_kernel(const float* __restrict__ qin, const float* __restrict__ a_rel,
                        float* __restrict__ qr, int n) {
    __shared__ __align__(16) float qsh[256];
    int tid = threadIdx.x;
    int h = (tid >> 5) & 3;
    u64 w2[32];
    {
        const float* ab = a_rel + (size_t)tid * 32;
#pragma unroll
        for (int e = 0; e < 32; e++) w2[e] = packdup(ab[e]);
    }
    for (int n0 = blockIdx.x * 2; n0 < n; n0 += gridDim.x * 2) {
        __syncthreads();
        if (tid < 256) {
            int c = tid >> 1, which = tid & 1;
            int node = n0 + which;
            qsh[tid] = (node < n) ? qin[(size_t)node * 128 + c] : 0.f;
        }
        __syncthreads();
        u64 acc = 0ull;
        const u64* qp = (const u64*)qsh + h * 32;
#pragma unroll
        for (int e = 0; e < 32; e++) fma2(acc, qp[e], w2[e]);
        float a0, a1;
        unpack2(acc, a0, a1);
        qr[(size_t)n0 * 512 + tid] = a0;
        if (n0 + 1 < n) qr[(size_t)(n0 + 1) * 512 + tid] = a1;
    }
}

// ================= fused edge attention v3b: 512 threads (16 warps) per block =================
__global__ __launch_bounds__(512)
void edge_attn_kernel(const float* __restrict__ qr, const int* __restrict__ offs,
                      const int* __restrict__ ssrc, const float* __restrict__ p_rel,
                      const float* __restrict__ m_rel, float* __restrict__ attn) {
    extern __shared__ float msh[];   // 16384 floats = 64KB : m_rel[r][h][d][e]
    for (int i = threadIdx.x; i < 4096; i += 512)
        ((float4*)msh)[i] = ((const float4*)m_rel)[i];
    __syncthreads();

    int lane = threadIdx.x & 31;
    int h = lane >> 3, l0 = lane & 7;
    int gwarp = blockIdx.x * EA_WPB + ((int)threadIdx.x >> 5);
    const float SCALE = 0.17677669529663687f;

    for (int node = gwarp; node < NN; node += EA_WARPS) {
        float4 o4 = make_float4(0.f, 0.f, 0.f, 0.f);
        int obase = node * 4;
#pragma unroll
        for (int r = 0; r < 4; r++) {
            int s = offs[obase + r], e = offs[obase + r + 1];
            if (s >= e) continue;
            float4 q4 = *(const float4*)(qr + (size_t)node * 512 + r * 128 + lane * 4);
            float pr = p_rel[r * 4 + h] * SCALE;
            float m = -INFINITY, z = 0.f;
            float4 a4 = make_float4(0.f, 0.f, 0.f, 0.f);

            int src0 = __ldg(&ssrc[s]);
            float4 k_cur = *(const float4*)(g_k + (size_t)src0 * 128 + lane * 4);
            float4 v_cur = *(const float4*)(g_v + (size_t)src0 * 128 + lane * 4);

            for (int pos = s; pos < e; pos++) {
                float4 k4 = k_cur, v4 = v_cur;
                if (pos + 1 < e) {
                    int srcn = __ldg(&ssrc[pos + 1]);
                    k_cur = *(const float4*)(g_k + (size_t)srcn * 128 + lane * 4);
                    v_cur = *(const float4*)(g_v + (size_t)srcn * 128 + lane * 4);
                }
                float sc = q4.x * k4.x + q4.y * k4.y + q4.z * k4.z + q4.w * k4.w;
                sc += __shfl_xor_sync(0xffffffffu, sc, 1);
                sc += __shfl_xor_sync(0xffffffffu, sc, 2);
                sc += __shfl_xor_sync(0xffffffffu, sc, 4);
                sc *= pr;
                float nm = fmaxf(m, sc);
                float eo = __expf(m - nm);
                float es = __expf(sc - nm);
                z = z * eo + es;
                a4.x = a4.x * eo + es * v4.x;
                a4.y = a4.y * eo + es * v4.y;
                a4.z = a4.z * eo + es * v4.z;
                a4.w = a4.w * eo + es * v4.w;
                m = nm;
            }
            float iz = 1.0f / z;
            float w0 = a4.x * iz, w1 = a4.y * iz, w2 = a4.z * iz, w3 = a4.w * iz;

            // o_e += sum_d M[r][h][d][e] * w_d  via 8-lane butterfly
            const float* Mb = msh + (r * 4 + h) * 1024;
            int eb = l0 * 4;
#pragma unroll
            for (int j = 0; j < 8; j++) {
                int gsrc = (l0 + j) & 7;
                int srclane = (h << 3) | gsrc;
                float wa = __shfl_sync(0xffffffffu, w0, srclane);
                float wb = __shfl_sync(0xffffffffu, w1, srclane);
                float wc = __shfl_sync(0xffffffffu, w2, srclane);
                float wd = __shfl_sync(0xffffffffu, w3, srclane);
                const float* Mr = Mb + (gsrc * 4) * 32 + eb;
                float4 m0 = *(const float4*)(Mr);
                float4 m1 = *(const float4*)(Mr + 32);
                float4 m2 = *(const float4*)(Mr + 64);
                float4 m3 = *(const float4*)(Mr + 96);
                o4.x += wa * m0.x + wb * m1.x + wc * m2.x + wd * m3.x;
                o4.y += wa * m0.y + wb * m1.y + wc * m2.y + wd * m3.y;
                o4.z += wa * m0.z + wb * m1.z + wc * m2.z + wd * m3.z;
                o4.w += wa * m0.w + wb * m1.w + wc * m2.w + wd * m3.w;
            }
        }
        *(float4*)(attn + (size_t)node * 128 + lane * 4) = o4;
    }
}

// ---------------- BatchNorm ----------------
__global__ __launch_bounds__(512)
void bn_stats_kernel(const float* __restrict__ h, float* __restrict__ stats, int n) {
    __shared__ float4 s_sum[16][32];
    __shared__ float4 s_sq[16][32];
    int tid = threadIdx.x;
    int c4 = tid & 31;
    int rg = tid >> 5;
    float4 sum = make_float4(0.f, 0.f, 0.f, 0.f);
    float4 sq  = make_float4(0.f, 0.f, 0.f, 0.f);
    for (int r = blockIdx.x * 16 + rg; r < n; r += gridDim.x * 16) {
        float4 v = *(const float4*)(h + (size_t)r * 128 + c4 * 4);
        sum.x += v.x; sum.y += v.y; sum.z += v.z; sum.w += v.w;
        sq.x += v.x * v.x; sq.y += v.y * v.y; sq.z += v.z * v.z; sq.w += v.w * v.w;
    }
    s_sum[rg][c4] = sum; s_sq[rg][c4] = sq;
    __syncthreads();
#pragma unroll
    for (int step = 8; step >= 1; step >>= 1) {
        if (rg < step) {
            float4 a = s_sum[rg][c4], b = s_sum[rg + step][c4];
            a.x += b.x; a.y += b.y; a.z += b.z; a.w += b.w;
            s_sum[rg][c4] = a;
            float4 e = s_sq[rg][c4], f = s_sq[rg + step][c4];
            e.x += f.x; e.y += f.y; e.z += f.z; e.w += f.w;
            s_sq[rg][c4] = e;
        }
        __syncthreads();
    }
    if (rg == 0) {
        float4 a = s_sum[0][c4], e = s_sq[0][c4];
        atomicAdd(&stats[c4 * 4 + 0], a.x);
        atomicAdd(&stats[c4 * 4 + 1], a.y);
        atomicAdd(&stats[c4 * 4 + 2], a.z);
        atomicAdd(&stats[c4 * 4 + 3], a.w);
        atomicAdd(&stats[128 + c4 * 4 + 0], e.x);
        atomicAdd(&stats[128 + c4 * 4 + 1], e.y);
        atomicAdd(&stats[128 + c4 * 4 + 2], e.z);
        atomicAdd(&stats[128 + c4 * 4 + 3], e.w);
    }
}

__global__ void bn_apply_kernel(float* __restrict__ h, const float* __restrict__ stats,
                                const float* __restrict__ gamma, const float* __restrict__ beta,
                                int n) {
    int i = blockIdx.x * blockDim.x + threadIdx.x;
    if (i >= n * 32) return;
    int c4 = (i & 31) * 4;
    float4 hv = reinterpret_cast<float4*>(h)[i];
    float4 mu = *reinterpret_cast<const float4*>(stats + c4);
    float4 sg = *reinterpret_cast<const float4*>(stats + 128 + c4);
    float4 ga = *reinterpret_cast<const float4*>(gamma + c4);
    float4 be = *reinterpret_cast<const float4*>(beta + c4);
    const float inv = 1.0f / (float)NN;
    float m0 = mu.x * inv, m1 = mu.y * inv, m2 = mu.z * inv, m3 = mu.w * inv;
    hv.x = (hv.x - m0) * rsqrtf(sg.x * inv - m0 * m0 + 1e-5f) * ga.x + be.x;
    hv.y = (hv.y - m1) * rsqrtf(sg.y * inv - m1 * m1 + 1e-5f) * ga.y + be.y;
    hv.z = (hv.z - m2) * rsqrtf(sg.z * inv - m2 * m2 + 1e-5f) * ga.z + be.z;
    hv.w = (hv.w - m3) * rsqrtf(sg.w * inv - m3 * m3 + 1e-5f) * ga.w + be.w;
    reinterpret_cast<float4*>(h)[i] = hv;
}

// ---------------- gather ----------------
__global__ void gather_kernel(const int* __restrict__ idx, const float* __restrict__ h,
                              float* __restrict__ out) {
    int gid = blockIdx.x * blockDim.x + threadIdx.x;
    if (gid >= MMOUT * 32) return;
    int m = gid >> 5, c4 = gid & 31;
    reinterpret_cast<float4*>(out)[(size_t)m * 32 + c4] =
        reinterpret_cast<const float4*>(h + (size_t)idx[m] * 128)[c4];
}

// ---------------- launch ----------------
extern "C" void kernel_launch(void* const* d_in, const int* in_sizes, int n_in,
                              void* d_out, int out_size) {
    const float* x        = (const float*)d_in[0];
    const float* proj_w   = (const float*)d_in[1];
    const float* proj_b   = (const float*)d_in[2];
    const float* bn_gamma = (const float*)d_in[3];
    const float* bn_beta  = (const float*)d_in[4];
    const float* q_w      = (const float*)d_in[5];
    const float* q_b      = (const float*)d_in[6];
    const float* k_w      = (const float*)d_in[7];
    const float* k_b      = (const float*)d_in[8];
    const float* v_w      = (const float*)d_in[9];
    const float* v_b      = (const float*)d_in[10];
    const float* a_w      = (const float*)d_in[11];
    const float* a_b      = (const float*)d_in[12];
    const float* skip     = (const float*)d_in[13];
    const float* a_rel    = (const float*)d_in[14];
    const float* m_rel    = (const float*)d_in[15];
    const float* p_rel    = (const float*)d_in[16];
    const int*   edge_idx = (const int*)d_in[17];
    const int*   edge_typ = (const int*)d_in[18];
    const int*   idx      = (const int*)d_in[19];
    float*       out      = (float*)d_out;

    float *p_h, *p_q, *p_k, *p_v, *p_qr, *p_attn, *p_stats;
    int *p_counts, *p_offs, *p_cursor, *p_bsum, *p_boff, *p_ssrc;
    __nv_bfloat16* p_wimg;
    cudaGetSymbolAddress((void**)&p_h, g_h);
    cudaGetSymbolAddress((void**)&p_q, g_q);
    cudaGetSymbolAddress((void**)&p_k, g_k);
    cudaGetSymbolAddress((void**)&p_v, g_v);
    cudaGetSymbolAddress((void**)&p_qr, g_qr);
    cudaGetSymbolAddress((void**)&p_attn, g_attn);
    cudaGetSymbolAddress((void**)&p_stats, g_stats);
    cudaGetSymbolAddress((void**)&p_counts, g_counts);
    cudaGetSymbolAddress((void**)&p_offs, g_offs);
    cudaGetSymbolAddress((void**)&p_cursor, g_cursor);
    cudaGetSymbolAddress((void**)&p_bsum, g_bsum);
    cudaGetSymbolAddress((void**)&p_boff, g_boff);
    cudaGetSymbolAddress((void**)&p_ssrc, g_ssrc);
    cudaGetSymbolAddress((void**)&p_wimg, g_wimg);

    cudaFuncSetAttribute(gemm_tc<0>, cudaFuncAttributeMaxDynamicSharedMemorySize, GS_TOTAL);
    cudaFuncSetAttribute(gemm_tc<1>, cudaFuncAttributeMaxDynamicSharedMemorySize, GS_TOTAL);
    cudaFuncSetAttribute(edge_attn_kernel, cudaFuncAttributeMaxDynamicSharedMemorySize, 65536);

    const int gemmGrid = (NN + 127) / 128;   // 391
    const int eBlocks = (EE + 255) / 256;

    const __nv_bfloat16* imgP  = p_wimg;
    const __nv_bfloat16* imgQ0 = p_wimg + 1 * 32768;
    const __nv_bfloat16* imgQ1 = p_wimg + 2 * 32768;
    const __nv_bfloat16* imgK0 = p_wimg + 3 * 32768;
    const __nv_bfloat16* imgK1 = p_wimg + 4 * 32768;
    const __nv_bfloat16* imgV0 = p_wimg + 5 * 32768;
    const __nv_bfloat16* imgV1 = p_wimg + 6 * 32768;
    const __nv_bfloat16* imgA0 = p_wimg + 7 * 32768;
    const __nv_bfloat16* imgA1 = p_wimg + 8 * 32768;

    // launches 0-3 (gemm proj in profiled slot = launch index 3)
    fill_zero_kernel<<<1, 256>>>((unsigned*)p_stats, 2 * HIDN);
    wprep_kernel<<<9, 128>>>(proj_w, q_w, k_w, v_w, a_w);
    fill_zero_kernel<<<(NSEG + 255) / 256, 256>>>((unsigned*)p_counts, NSEG);
    gemm_tc<0><<<dim3(gemmGrid, 1), 256, GS_TOTAL>>>(x, imgP, imgP, imgP,
                                                     proj_b, proj_b, proj_b,
                                                     p_h, p_h, p_h, NN, nullptr, nullptr);

    // ---- CSR build (independent of h) ----
    hist_kernel<<<eBlocks, 256>>>(edge_idx, edge_typ, p_counts);
    scan_pass1<<<SCAN_B, 1024>>>(p_counts, p_bsum);
    scan_pass2<<<1, 32>>>(p_bsum, p_boff, p_offs);
    scan_pass3<<<SCAN_B, 1024>>>(p_counts, p_boff, p_offs, p_cursor);
    scatter_kernel<<<eBlocks, 256>>>(edge_idx, edge_typ, p_cursor, p_ssrc);

    // ---- BN ----
    bn_stats_kernel<<<592, 512>>>(p_h, p_stats, NN);
    bn_apply_kernel<<<(NN * 32 + 255) / 256, 256>>>(p_h, p_stats, bn_gamma, bn_beta, NN);

    // layer 0 fused QKV
    gemm_tc<0><<<dim3(gemmGrid, 3), 256, GS_TOTAL>>>(p_h, imgQ0, imgK0, imgV0,
                                                     q_b, k_b, v_b,
                                                     p_q, p_k, p_v, NN, nullptr, nullptr);

    for (int l = 0; l < LLAY; l++) {
        const float* abl = a_b + (size_t)l * 128;
        const float* arl = a_rel + (size_t)l * RR * HH * DDIM * DDIM;
        const float* mrl = m_rel + (size_t)l * RR * HH * DDIM * DDIM;
        const float* prl = p_rel + (size_t)l * RR * HH;
        const float* skl = skip + l;
        const __nv_bfloat16* imgA = (l == 0) ? imgA0 : imgA1;

        if (l > 0) {
            gemm_tc<0><<<dim3(gemmGrid, 3), 256, GS_TOTAL>>>(
                p_h, imgQ1, imgK1, imgV1,
                q_b + 128, k_b + 128, v_b + 128,
                p_q, p_k, p_v, NN, nullptr, nullptr);
        }

        q_transform_kernel<<<592, 512>>>(p_q, arl, p_qr, NN);

        edge_attn_kernel<<<EA_BLOCKS, 512, 65536>>>(p_qr, p_offs, p_ssrc, prl, mrl, p_attn);

        gemm_tc<1><<<dim3(gemmGrid, 1), 256, GS_TOTAL>>>(p_attn, imgA, imgA, imgA,
                                                         abl, abl, abl,
                                                         p_h, p_h, p_h, NN, p_h, skl);
    }

    gather_kernel<<<(MMOUT * 32 + 255) / 256, 256>>>(idx, p_h, out);
}